// round 11
// baseline (speedup 1.0000x reference)
#include <cuda_runtime.h>
#include <cuda_fp16.h>
#include <cstdint>

#define NUM_OBS 100000
#define NUM_ACT 10
#define RD 64
#define MAXB 8192
#define BM 64
#define BN 64
#define THREADS 128
#define OFF_A 0
#define OFF_B 8192            // A: 64 rows x 128B = 8KB; B: 64 rows x 128B = 8KB
#define CSTRIDE 72            // staged-C row stride in floats (8-bank/row shift)
#define SMEM_BYTES (BM * CSTRIDE * 4)  // 18432 B; C staging overlays dead operands

// Gathered fp16 operands (2 MB). Device globals = sanctioned scratch.
__device__ __half g_F16[MAXB * RD];
__device__ __half g_B16[MAXB * RD];

__device__ __forceinline__ int clampi(int v, int lo, int hi) {
    return v < lo ? lo : (v > hi ? hi : v);
}

// 8 batch rows per 256-thread block; 32 lanes/row, float2 -> half2 per lane.
__global__ void gather_kernel(
    const int* __restrict__ obs, const int* __restrict__ act,
    const int* __restrict__ fobs, const int* __restrict__ fact,
    const float* __restrict__ Wf, const float* __restrict__ Wb,
    int Btot)
{
    int i = blockIdx.x * 8 + (threadIdx.x >> 5);
    int lane = threadIdx.x & 31;
    if (i >= Btot) return;
    {
        int o = clampi(obs[i], 0, NUM_OBS - 1);
        int a = clampi(act[i], 0, NUM_ACT - 1);
        long long idx = (long long)o * NUM_ACT + a;
        float2 v = *(const float2*)(Wf + idx * RD + lane * 2);
        *(__half2*)(g_F16 + i * RD + lane * 2) = __floats2half2_rn(v.x, v.y);
    }
    {
        int o = clampi(fobs[i], 0, NUM_OBS - 1);
        int a = clampi(fact[i], 0, NUM_ACT - 1);
        long long idx = (long long)o * NUM_ACT + a;
        float2 v = *(const float2*)(Wb + idx * RD + lane * 2);
        *(__half2*)(g_B16 + i * RD + lane * 2) = __floats2half2_rn(v.x, v.y);
    }
}

__device__ __forceinline__ uint32_t smem_u32(const void* p) {
    uint32_t a;
    asm("{ .reg .u64 t; cvta.to.shared.u64 t, %1; cvt.u32.u64 %0, t; }"
        : "=r"(a) : "l"(p));
    return a;
}

__device__ __forceinline__ void cp_async16(uint32_t dst, const void* src) {
    asm volatile("cp.async.cg.shared.global [%0], [%1], 16;"
                 :: "r"(dst), "l"(src));
}

__device__ __forceinline__ void ldsm_x4(uint32_t& r0, uint32_t& r1,
                                        uint32_t& r2, uint32_t& r3,
                                        uint32_t addr)
{
    asm volatile(
        "ldmatrix.sync.aligned.m8n8.x4.shared.b16 {%0,%1,%2,%3}, [%4];"
        : "=r"(r0), "=r"(r1), "=r"(r2), "=r"(r3)
        : "r"(addr));
}

__device__ __forceinline__ void mma16816_f16(float* c, const uint32_t* a,
                                             const uint32_t* b)
{
    asm volatile(
        "mma.sync.aligned.m16n8k16.row.col.f32.f16.f16.f32 "
        "{%0,%1,%2,%3}, {%4,%5,%6,%7}, {%8,%9}, {%0,%1,%2,%3};"
        : "+f"(c[0]), "+f"(c[1]), "+f"(c[2]), "+f"(c[3])
        : "r"(a[0]), "r"(a[1]), "r"(a[2]), "r"(a[3]),
          "r"(b[0]), "r"(b[1]));
}

__device__ __forceinline__ void stg_cs_128(float* p, float4 v) {
    asm volatile("st.global.cs.v4.f32 [%0], {%1,%2,%3,%4};"
                 :: "l"(p), "f"(v.x), "f"(v.y), "f"(v.z), "f"(v.w)
                 : "memory");
}

// out[i][j] = F[i].B[j], single-pass fp16 HMMA, fp32 accumulation.
// CTA tile 64x64, 4 warps of 32(M)x32(N), K=64 resident. 18.4KB smem +
// <=64 regs -> 8 CTAs/SM: many independent compute/store phase streams.
__global__ void __launch_bounds__(THREADS, 8) fb_gemm_kernel(
    float* __restrict__ out, int Btot)
{
    extern __shared__ __align__(16) uint8_t smem[];
    const uint32_t sbase = smem_u32(smem);
    const int tid = threadIdx.x;
    const int tileM = blockIdx.y * BM;
    const int tileN = blockIdx.x * BN;

    // ---- fill smem via cp.async (SW128 swizzle: 16B chunk ^ (row&7)) ----
    {
        const uint4* srcA = (const uint4*)g_F16;  // 8 uint4 per 64-half row
        const uint4* srcB = (const uint4*)g_B16;
#pragma unroll
        for (int it = 0; it < 4; it++) {
            int t = tid + it * THREADS;       // 0..511
            int r = t >> 3, ch = t & 7;
            uint32_t sw = ((ch ^ (r & 7)) << 4);
            uint32_t soffA = OFF_A + r * 128 + sw;
            uint32_t soffB = OFF_B + r * 128 + sw;
            int ga = tileM + r, gb = tileN + r;
            if (ga < Btot) cp_async16(sbase + soffA, srcA + ga * 8 + ch);
            else *(uint4*)(smem + soffA) = make_uint4(0u, 0u, 0u, 0u);
            if (gb < Btot) cp_async16(sbase + soffB, srcB + gb * 8 + ch);
            else *(uint4*)(smem + soffB) = make_uint4(0u, 0u, 0u, 0u);
        }
        asm volatile("cp.async.commit_group;");
        asm volatile("cp.async.wait_group 0;");
    }
    __syncthreads();

    const int wid = tid >> 5, lane = tid & 31;
    const int m0w = (wid & 1) * 32;   // 2 warps over M
    const int n0w = (wid >> 1) * 32;  // 2 warps over N

    // ldmatrix per-lane addressing: lanes in 4 groups of 8.
    const int lr = lane & 7;
    const int lq = lane >> 3;
    const int row_add = lr + (lq & 1) * 8;   // +8 rows for groups 1,3
    const int kb_add = (lq >> 1) * 16;       // +16 B (k+8) for groups 2,3
    const int swz = lr << 4;                 // SW128 xor: (row&7)<<4 == lr<<4

    float c[2][4][4];
#pragma unroll
    for (int mf = 0; mf < 2; mf++)
#pragma unroll
        for (int nf = 0; nf < 4; nf++)
#pragma unroll
            for (int r = 0; r < 4; r++) c[mf][nf][r] = 0.0f;

#pragma unroll
    for (int ks = 0; ks < 4; ks++) {
        int kb = ks * 32;  // byte offset within 128 B row
        uint32_t a[2][4];
#pragma unroll
        for (int mf = 0; mf < 2; mf++) {
            int row = m0w + mf * 16 + row_add;
            uint32_t addr = sbase + OFF_A + row * 128 + ((kb + kb_add) ^ swz);
            ldsm_x4(a[mf][0], a[mf][1], a[mf][2], a[mf][3], addr);
        }
        uint32_t b[4][2];
#pragma unroll
        for (int nh = 0; nh < 2; nh++) {
            int row = n0w + nh * 16 + row_add;
            uint32_t addr = sbase + OFF_B + row * 128 + ((kb + kb_add) ^ swz);
            uint32_t r0, r1, r2, r3;
            ldsm_x4(r0, r1, r2, r3, addr);
            b[nh * 2 + 0][0] = r0;
            b[nh * 2 + 1][0] = r1;
            b[nh * 2 + 0][1] = r2;
            b[nh * 2 + 1][1] = r3;
        }
#pragma unroll
        for (int mf = 0; mf < 2; mf++)
#pragma unroll
            for (int nf = 0; nf < 4; nf++)
                mma16816_f16(c[mf][nf], a[mf], b[nf]);
    }

    // ---- epilogue: stage C in smem (overlays dead operand region), then
    //      fully coalesced streaming STG.128 ----
    __syncthreads();  // operand smem dead from here; safe to overwrite
    {
        float* cs = (float*)smem;
        const int gid = lane >> 2, qid = lane & 3;
#pragma unroll
        for (int mf = 0; mf < 2; mf++) {
            int r0 = m0w + mf * 16 + gid;
#pragma unroll
            for (int nf = 0; nf < 4; nf++) {
                int col = n0w + nf * 8 + qid * 2;
                *(float2*)(cs + r0 * CSTRIDE + col) =
                    make_float2(c[mf][nf][0], c[mf][nf][1]);
                *(float2*)(cs + (r0 + 8) * CSTRIDE + col) =
                    make_float2(c[mf][nf][2], c[mf][nf][3]);
            }
        }
    }
    __syncthreads();
    {
        const float* cs = (const float*)smem;
        // 2 rows per instruction: 32 lanes x float4 cover 2 x 64 floats.
        const int rsub = lane >> 4;           // 0,1
        const int csub = lane & 15;           // 16 lanes x 4 floats = 64 cols
#pragma unroll
        for (int i = 0; i < 8; i++) {
            int lrow = wid * 16 + i * 2 + rsub;   // 4 warps x 16 rows
            int grow = tileM + lrow;
            if (grow >= Btot) continue;
            float4 v = *(const float4*)(cs + lrow * CSTRIDE + csub * 4);
            int gcol = tileN + csub * 4;
            if (tileN + BN <= Btot) {
                stg_cs_128(out + (size_t)grow * Btot + gcol, v);
            } else {
                float vv[4] = { v.x, v.y, v.z, v.w };
                for (int j = 0; j < 4; j++)
                    if (gcol + j < Btot)
                        out[(size_t)grow * Btot + gcol + j] = vv[j];
            }
        }
    }
}

extern "C" void kernel_launch(void* const* d_in, const int* in_sizes, int n_in,
                              void* d_out, int out_size)
{
    const int* obs  = (const int*)d_in[0];
    const int* act  = (const int*)d_in[1];
    const int* fobs = (const int*)d_in[2];
    const int* fact = (const int*)d_in[3];
    const float* Wf = (const float*)d_in[4];
    const float* Wb = (const float*)d_in[5];
    float* out = (float*)d_out;
    int Btot = in_sizes[0];

    gather_kernel<<<(Btot + 7) / 8, 256>>>(obs, act, fobs, fact, Wf, Wb, Btot);

    cudaFuncSetAttribute(fb_gemm_kernel,
                         cudaFuncAttributeMaxDynamicSharedMemorySize,
                         SMEM_BYTES);
    dim3 grid((Btot + BN - 1) / BN, (Btot + BM - 1) / BM);
    fb_gemm_kernel<<<grid, THREADS, SMEM_BYTES>>>(out, Btot);
}